// round 4
// baseline (speedup 1.0000x reference)
#include <cuda_runtime.h>
#include <math.h>
#include <float.h>

#define NB 2048
#define ND 256
#define NS 64
#define NK 1024
#define TD 512          // 2*D
#define SD (NS*ND)      // 16384
#define BETA 0.25f

// ---------------- device scratch (static device globals = allowed scratch) ----
__device__ float g_mr[(size_t)NB*SD];   // memory state real (134MB)
__device__ float g_mi[(size_t)NB*SD];   // memory state imag (134MB)
__device__ float g_gr[NB*ND];           // current g real
__device__ float g_gi[NB*ND];           // current g imag
__device__ float g_zf[(size_t)NB*TD];   // concat(cr,ci) per iter
__device__ float g_eff[NB*NS];          // effective write weights
__device__ float g_ysq[NK];             // ||codebook_k||^2
__device__ float g_pscore[NB*8];        // per-k-tile argmin partials
__device__ int   g_pidx[NB*8];
__device__ int   g_hist[NK];
__device__ float g_aux;

// ---------------- helpers ----------------
__device__ __forceinline__ float warp_sum(float v){
    #pragma unroll
    for(int o=16;o;o>>=1) v += __shfl_xor_sync(0xffffffffu, v, o);
    return v;
}
__device__ __forceinline__ float warp_max(float v){
    #pragma unroll
    for(int o=16;o;o>>=1) v = fmaxf(v, __shfl_xor_sync(0xffffffffu, v, o));
    return v;
}

// ---------------- copy inputs -> g state ----------------
__global__ void k_copyg(const float* __restrict__ gr, const float* __restrict__ gi){
    int t = blockIdx.x*512 + threadIdx.x;   // 1024 blocks * 512 = 524288 = NB*ND
    g_gr[t] = gr[t];
    g_gi[t] = gi[t];
}

// ---------------- init: ysq, zero hist/aux ----------------
__global__ void k_init(const float* __restrict__ cb){
    int gt = blockIdx.x*256 + threadIdx.x;  // 128 blocks * 256 = 32768 = 1024 warps
    int w = gt >> 5, lane = gt & 31;
    const float* row = cb + (size_t)w*TD;
    float p = 0.f;
    for(int j=lane;j<TD;j+=32) p += row[j]*row[j];
    p = warp_sum(p);
    if(lane==0) g_ysq[w] = p;
    if(gt < NK) g_hist[gt] = 0;
    if(gt == 0) g_aux = 0.f;
}

// ---------------- write-address net: gate, softmax, entropy, top-3, eff -------
__global__ void __launch_bounds__(256) k_addr(const float* __restrict__ aw,
                                              const float* __restrict__ ab,
                                              const float* __restrict__ gw,
                                              const float* __restrict__ gb)
{
    extern __shared__ float sm[];
    float* s_aw   = sm;                // 64*512 = 32768
    float* s_gw   = sm + 32768;        // 512
    float* s_flat = s_gw + 512;        // 512
    float* s_log  = s_flat + 512;      // 64
    int t = threadIdx.x, wid = t>>5, lane = t&31;

    {
        const float4* a4 = (const float4*)aw; float4* s4 = (float4*)s_aw;
        for(int i=t;i<8192;i+=256) s4[i] = a4[i];
        const float4* g4 = (const float4*)gw; float4* sg = (float4*)s_gw;
        if(t<128) sg[t] = g4[t];
    }
    __syncthreads();

    float ent_acc = 0.f;
    float gbv = gb[0];

    for(int bi=0;bi<32;bi++){
        int b = blockIdx.x*32 + bi;
        s_flat[t]     = g_gr[b*ND + t];
        s_flat[256+t] = g_gi[b*ND + t];
        __syncthreads();

        #pragma unroll
        for(int r=0;r<8;r++){
            int s = wid*8 + r;
            const float* row = s_aw + s*TD;
            float p = 0.f;
            #pragma unroll 4
            for(int j=lane;j<TD;j+=32) p += s_flat[j]*row[j];
            p = warp_sum(p);
            if(lane==0) s_log[s] = p + ab[s];
        }
        __syncthreads();

        if(wid==0){
            // gate
            float gp = 0.f;
            #pragma unroll 4
            for(int j=lane;j<TD;j+=32) gp += s_flat[j]*s_gw[j];
            gp = warp_sum(gp);
            float gate = 1.f/(1.f + expf(-(gp + gbv)));
            // softmax over 64 logits (2 per lane)
            float v0 = s_log[lane], v1 = s_log[lane+32];
            float m  = warp_max(fmaxf(v0,v1));
            float e0 = expf(v0-m), e1 = expf(v1-m);
            float ssum = warp_sum(e0+e1);
            float w0 = e0/ssum, w1 = e1/ssum;
            ent_acc += -(w0*logf(w0+1e-10f)) - (w1*logf(w1+1e-10f));
            // top-3 (first-index tie break, matches lax.top_k)
            float a0=w0, a1=w1; int i0=lane, i1=lane+32;
            float tv[3]; int ti[3];
            #pragma unroll
            for(int p3=0;p3<3;p3++){
                float v; int ix;
                if(a0>a1 || (a0==a1 && i0<i1)){ v=a0; ix=i0; } else { v=a1; ix=i1; }
                #pragma unroll
                for(int o=16;o;o>>=1){
                    float ov = __shfl_xor_sync(0xffffffffu, v, o);
                    int   oi = __shfl_xor_sync(0xffffffffu, ix, o);
                    if(ov>v || (ov==v && oi<ix)){ v=ov; ix=oi; }
                }
                tv[p3]=v; ti[p3]=ix;
                if(i0==ix) a0 = -1.f;
                if(i1==ix) a1 = -1.f;
            }
            float norm = 1.f/(tv[0]+tv[1]+tv[2]+1e-6f);
            float o0=0.f, o1=0.f;
            #pragma unroll
            for(int p3=0;p3<3;p3++){
                if(lane==ti[p3])    o0 = tv[p3]*norm;
                if(lane+32==ti[p3]) o1 = tv[p3]*norm;
            }
            g_eff[b*NS+lane]    = gate*o0;
            g_eff[b*NS+lane+32] = gate*o1;
        }
        __syncthreads();
    }
    if(wid==0){
        float es = warp_sum(ent_acc);
        if(lane==0) atomicAdd(&g_aux, es*(1.f/(float)NB));
    }
}

// ---------------- fused assoc-mem + complex layernorm (1 CTA per b) ----------
__global__ void __launch_bounds__(512) k_mem(const float* __restrict__ mr_in,
                                             const float* __restrict__ mi_in,
                                             int first,
                                             const float* __restrict__ lnrw, const float* __restrict__ lnrb,
                                             const float* __restrict__ lniw, const float* __restrict__ lnib,
                                             const float* __restrict__ clns, const float* __restrict__ clnb)
{
    extern __shared__ float sm[];
    float* s_mr  = sm;                 // 16384
    float* s_mi  = s_mr + SD;          // 16384
    float* s_gr  = s_mi + SD;          // 256
    float* s_gi  = s_gr + ND;          // 256
    float* s_rr  = s_gi + ND;          // 256
    float* s_ri  = s_rr + ND;          // 256
    float* s_sim = s_ri + ND;          // 64
    float* s_attn= s_sim + NS;         // 64
    float* s_eff = s_attn + NS;        // 64
    float* s_red = s_eff + NS;         // 16
    float* s_scal= s_red + 16;         // 2

    int b = blockIdx.x, t = threadIdx.x, wid = t>>5, lane = t&31;
    const float* mrs = first ? (mr_in + (size_t)b*SD) : (g_mr + (size_t)b*SD);
    const float* mis = first ? (mi_in + (size_t)b*SD) : (g_mi + (size_t)b*SD);

    {
        const float4* a4 = (const float4*)mrs;
        const float4* b4 = (const float4*)mis;
        float4* sa = (float4*)s_mr; float4* sb = (float4*)s_mi;
        #pragma unroll
        for(int i=0;i<8;i++) sa[t + i*512] = a4[t + i*512];
        #pragma unroll
        for(int i=0;i<8;i++) sb[t + i*512] = b4[t + i*512];
    }
    if(t<ND){ s_gr[t] = g_gr[b*ND+t]; } else { s_gi[t-ND] = g_gi[b*ND + (t-ND)]; }
    if(t<NS) s_eff[t] = g_eff[b*NS+t];
    __syncthreads();

    // sim[s] = sum_d mr*gr + mi*gi     (16 warps x 4 rows)
    #pragma unroll
    for(int r=0;r<4;r++){
        int s = wid*4 + r;
        const float* pr = s_mr + s*ND;
        const float* pi = s_mi + s*ND;
        float p = 0.f;
        #pragma unroll
        for(int i=0;i<8;i++){
            int d = lane + i*32;
            p += pr[d]*s_gr[d] + pi[d]*s_gi[d];
        }
        p = warp_sum(p);
        if(lane==0) s_sim[s] = p;
    }
    __syncthreads();

    // softmax over S=64 (warp 0)
    if(wid==0){
        float v0 = s_sim[lane], v1 = s_sim[lane+32];
        float m  = warp_max(fmaxf(v0,v1));
        float e0 = expf(v0-m), e1 = expf(v1-m);
        float ssum = warp_sum(e0+e1);
        s_attn[lane]    = e0/ssum;
        s_attn[lane+32] = e1/ssum;
    }
    __syncthreads();

    // read_r / read_i  (threads 0..255 real, 256..511 imag)
    {
        float acc = 0.f;
        if(t < ND){
            const float* base = s_mr + t;
            #pragma unroll 8
            for(int s=0;s<NS;s++) acc += s_attn[s]*base[s*ND];
            s_rr[t] = acc;
        } else {
            int d = t - ND;
            const float* base = s_mi + d;
            #pragma unroll 8
            for(int s=0;s<NS;s++) acc += s_attn[s]*base[s*ND];
            s_ri[d] = acc;
        }
    }
    __syncthreads();

    // memory update + per-row LayerNorm (biased var, eps 1e-6), write to g_mr/g_mi
    #pragma unroll
    for(int r=0;r<4;r++){
        int s = wid*4 + r;
        float e = s_eff[s];
        float om = 1.f - e;
        // real
        {
            float v[8]; float sumv = 0.f;
            #pragma unroll
            for(int i=0;i<8;i++){
                int d = lane + i*32;
                v[i] = om*s_mr[s*ND+d] + e*s_gr[d];
                sumv += v[i];
            }
            float mu = warp_sum(sumv) * (1.f/ND);
            float s2 = 0.f;
            #pragma unroll
            for(int i=0;i<8;i++){ float dd = v[i]-mu; s2 += dd*dd; }
            float var = warp_sum(s2) * (1.f/ND);
            float inv = 1.f/sqrtf(var + 1e-6f);
            #pragma unroll
            for(int i=0;i<8;i++){
                int d = lane + i*32;
                g_mr[(size_t)b*SD + s*ND + d] = (v[i]-mu)*inv*__ldg(&lnrw[d]) + __ldg(&lnrb[d]);
            }
        }
        // imag
        {
            float v[8]; float sumv = 0.f;
            #pragma unroll
            for(int i=0;i<8;i++){
                int d = lane + i*32;
                v[i] = om*s_mi[s*ND+d] + e*s_gi[d];
                sumv += v[i];
            }
            float mu = warp_sum(sumv) * (1.f/ND);
            float s2 = 0.f;
            #pragma unroll
            for(int i=0;i<8;i++){ float dd = v[i]-mu; s2 += dd*dd; }
            float var = warp_sum(s2) * (1.f/ND);
            float inv = 1.f/sqrtf(var + 1e-6f);
            #pragma unroll
            for(int i=0;i<8;i++){
                int d = lane + i*32;
                g_mi[(size_t)b*SD + s*ND + d] = (v[i]-mu)*inv*__ldg(&lniw[d]) + __ldg(&lnib[d]);
            }
        }
    }

    // complex layernorm on z = g + read  (threads 0..255 active; all hit syncs)
    float zr=0.f, zi=0.f, mag=0.f;
    if(t < ND){
        zr = s_gr[t] + s_rr[t];
        zi = s_gi[t] + s_ri[t];
        mag = sqrtf(zr*zr + zi*zi + 1e-8f);
    }
    float p = warp_sum(mag);
    if(lane==0) s_red[wid] = p;
    __syncthreads();
    if(t==0){
        float m2=0.f;
        #pragma unroll
        for(int i=0;i<8;i++) m2 += s_red[i];
        s_scal[0] = m2*(1.f/ND);
    }
    __syncthreads();
    float mean = s_scal[0];
    float dv = (t<ND) ? (mag-mean)*(mag-mean) : 0.f;
    p = warp_sum(dv);
    if(lane==0) s_red[wid] = p;
    __syncthreads();
    if(t==0){
        float v2=0.f;
        #pragma unroll
        for(int i=0;i<8;i++) v2 += s_red[i];
        float var = v2*(1.f/(ND-1));            // ddof=1
        s_scal[1] = 1.f/sqrtf(var + 1e-4f);
    }
    __syncthreads();
    if(t < ND){
        float nm = (mag-mean)*s_scal[1]*__ldg(&clns[t]) + __ldg(&clnb[t]);
        float h2 = zr*zr + zi*zi;
        float c, s;
        if(h2 > 0.f){ float ih = 1.f/sqrtf(h2); c = zr*ih; s = zi*ih; }
        else { c = 1.f; s = 0.f; }
        g_zf[(size_t)b*TD + t]      = nm*c;
        g_zf[(size_t)b*TD + ND + t] = nm*s;
    }
}

// ---------------- VQ distance GEMM + per-tile argmin ----------------
// grid (16, 8): x = b tile of 128, y = k tile of 128; 256 threads; 8x8 micro-tiles
#define VQ_DK 16
#define VQ_LD 132
__global__ void __launch_bounds__(256) k_vq(const float* __restrict__ cb){
    __shared__ float s_a[VQ_DK][VQ_LD];
    __shared__ float s_b[VQ_DK][VQ_LD];
    int tid = threadIdx.x;
    int tx = tid & 15, ty = tid >> 4;
    int b0 = blockIdx.x*128, k0 = blockIdx.y*128;

    float acc[8][8];
    #pragma unroll
    for(int i=0;i<8;i++)
        #pragma unroll
        for(int j=0;j<8;j++) acc[i][j] = 0.f;

    for(int ch=0; ch<TD/VQ_DK; ch++){
        int d0 = ch*VQ_DK;
        __syncthreads();
        #pragma unroll
        for(int l=0;l<2;l++){
            int q  = tid*2 + l;            // 0..511
            int r  = q >> 2;
            int c4 = (q & 3) * 4;
            float4 va = *(const float4*)&g_zf[(size_t)(b0+r)*TD + d0 + c4];
            s_a[c4+0][r]=va.x; s_a[c4+1][r]=va.y; s_a[c4+2][r]=va.z; s_a[c4+3][r]=va.w;
            float4 vb = *(const float4*)&cb[(size_t)(k0+r)*TD + d0 + c4];
            s_b[c4+0][r]=vb.x; s_b[c4+1][r]=vb.y; s_b[c4+2][r]=vb.z; s_b[c4+3][r]=vb.w;
        }
        __syncthreads();
        #pragma unroll
        for(int d=0; d<VQ_DK; d++){
            float af[8], bf[8];
            *(float4*)&af[0] = *(const float4*)&s_a[d][ty*8];
            *(float4*)&af[4] = *(const float4*)&s_a[d][ty*8+4];
            *(float4*)&bf[0] = *(const float4*)&s_b[d][tx*8];
            *(float4*)&bf[4] = *(const float4*)&s_b[d][tx*8+4];
            #pragma unroll
            for(int i=0;i<8;i++)
                #pragma unroll
                for(int j=0;j<8;j++) acc[i][j] += af[i]*bf[j];
        }
    }

    float ysq[8];
    #pragma unroll
    for(int j=0;j<8;j++) ysq[j] = __ldg(&g_ysq[k0 + tx*8 + j]);

    #pragma unroll
    for(int i=0;i<8;i++){
        float bv = FLT_MAX; int bi = 0x7fffffff;
        #pragma unroll
        for(int j=0;j<8;j++){
            float dvv = ysq[j] - 2.f*acc[i][j];
            int kk = k0 + tx*8 + j;
            if(dvv < bv){ bv = dvv; bi = kk; }     // ascending kk: strict < keeps lowest
        }
        #pragma unroll
        for(int o=1;o<16;o<<=1){
            float ov = __shfl_xor_sync(0xffffffffu, bv, o);
            int   oi = __shfl_xor_sync(0xffffffffu, bi, o);
            if(ov<bv || (ov==bv && oi<bi)){ bv=ov; bi=oi; }
        }
        if(tx==0){
            int b = b0 + ty*8 + i;
            g_pscore[b*8 + blockIdx.y] = bv;
            g_pidx  [b*8 + blockIdx.y] = bi;
        }
    }
}

// ---------------- final argmin, gather codebook, loss, histogram -------------
__global__ void __launch_bounds__(256) k_pick(const float* __restrict__ cb){
    int wid = threadIdx.x>>5, lane = threadIdx.x&31;
    int b = blockIdx.x*8 + wid;
    float bv = FLT_MAX; int bi = 0x7fffffff;
    if(lane < 8){ bv = g_pscore[b*8+lane]; bi = g_pidx[b*8+lane]; }
    #pragma unroll
    for(int o=1;o<32;o<<=1){
        float ov = __shfl_xor_sync(0xffffffffu, bv, o);
        int   oi = __shfl_xor_sync(0xffffffffu, bi, o);
        if(ov<bv || (ov==bv && oi<bi)){ bv=ov; bi=oi; }
    }
    bi = __shfl_sync(0xffffffffu, bi, 0);
    const float* row = cb + (size_t)bi*TD;
    float lacc = 0.f;
    for(int j=lane;j<TD;j+=32){
        float c = row[j], z = g_zf[(size_t)b*TD + j];
        float df = c - z; lacc += df*df;
        if(j < ND) g_gr[b*ND + j] = c;
        else       g_gi[b*ND + j - ND] = c;
    }
    lacc = warp_sum(lacc);
    if(lane==0){
        atomicAdd(&g_aux, BETA * lacc * (1.f/TD) * (1.f/NB));
        atomicAdd(&g_hist[bi], 1);
    }
}

// ---------------- codebook-usage entropy + hist reset ----------------
__global__ void __launch_bounds__(1024) k_ent(){
    __shared__ float s_red[32];
    int t = threadIdx.x;
    float pp = (float)g_hist[t] * (1.f/NB);
    float e = -pp * logf(pp + 1e-10f);
    g_hist[t] = 0;
    e = warp_sum(e);
    if((t&31)==0) s_red[t>>5] = e;
    __syncthreads();
    if(t < 32){
        float v = s_red[t];
        v = warp_sum(v);
        if(t==0) g_aux = g_aux + v * (1.f/6.931471805599453f);  // /log(1024)
    }
}

// ---------------- write output ----------------
__global__ void k_out(float* __restrict__ out, int out_n){
    int t = blockIdx.x*256 + threadIdx.x;   // 4096 blocks * 256 = 1048576
    int b = t >> 9, j = t & 511;
    out[t] = (j < ND) ? g_gr[b*ND + j] : g_gi[b*ND + j - ND];
    if(t == 0 && out_n > NB*TD) out[out_n-1] = g_aux;
}

// =============================================================================
extern "C" void kernel_launch(void* const* d_in, const int* in_sizes, int n_in,
                              void* d_out, int out_size)
{
    const float* gw_real = (const float*)d_in[0];
    const float* gw_imag = (const float*)d_in[1];
    const float* mem_real= (const float*)d_in[2];
    const float* mem_imag= (const float*)d_in[3];
    const float* gate_w  = (const float*)d_in[4];
    const float* gate_b  = (const float*)d_in[5];
    const float* addr_w  = (const float*)d_in[6];
    const float* addr_b  = (const float*)d_in[7];
    const float* lnr_w   = (const float*)d_in[8];
    const float* lnr_b   = (const float*)d_in[9];
    const float* lni_w   = (const float*)d_in[10];
    const float* lni_b   = (const float*)d_in[11];
    const float* cln_s   = (const float*)d_in[12];
    const float* cln_b   = (const float*)d_in[13];
    const float* codebook= (const float*)d_in[14];
    float* out = (float*)d_out;

    const int SMEM_ADDR = (64*512 + 512 + 512 + 64) * 4;
    const int SMEM_MEM  = (2*SD + 4*ND + 3*NS + 16 + 2) * 4;
    static int attr_done = 0;
    if(!attr_done){
        cudaFuncSetAttribute(k_addr, cudaFuncAttributeMaxDynamicSharedMemorySize, SMEM_ADDR);
        cudaFuncSetAttribute(k_mem,  cudaFuncAttributeMaxDynamicSharedMemorySize, SMEM_MEM);
        attr_done = 1;
    }

    k_copyg<<<1024, 512>>>(gw_real, gw_imag);
    k_init <<<128, 256>>>(codebook);

    for(int it=0; it<5; it++){
        k_addr<<<64, 256, SMEM_ADDR>>>(addr_w, addr_b, gate_w, gate_b);
        k_mem <<<NB, 512, SMEM_MEM>>>(mem_real, mem_imag, it==0 ? 1 : 0,
                                      lnr_w, lnr_b, lni_w, lni_b, cln_s, cln_b);
        k_vq  <<<dim3(16,8), 256>>>(codebook);
        k_pick<<<256, 256>>>(codebook);
        k_ent <<<1, 1024>>>();
    }
    k_out<<<4096, 256>>>(out, out_size);
}

// round 5
// speedup vs baseline: 1.3638x; 1.3638x over previous
#include <cuda_runtime.h>
#include <math.h>
#include <float.h>

#define NB 2048
#define ND 256
#define NS 64
#define NK 1024
#define TD 512          // 2*D
#define SD (NS*ND)      // 16384
#define BETA 0.25f

// ---------------- device scratch ----------------
__device__ float g_mr[(size_t)NB*SD];
__device__ float g_mi[(size_t)NB*SD];
__device__ float g_gr[NB*ND];
__device__ float g_gi[NB*ND];
__device__ float g_zf[(size_t)NB*TD];
__device__ float g_eff[NB*NS];
__device__ float g_ysq[NK];
__device__ float g_pscore[NB*8];
__device__ int   g_pidx[NB*8];
__device__ int   g_hist[NK];
__device__ float g_aux;

// ---------------- helpers ----------------
__device__ __forceinline__ float warp_sum(float v){
    #pragma unroll
    for(int o=16;o;o>>=1) v += __shfl_xor_sync(0xffffffffu, v, o);
    return v;
}
__device__ __forceinline__ float warp_max(float v){
    #pragma unroll
    for(int o=16;o;o>>=1) v = fmaxf(v, __shfl_xor_sync(0xffffffffu, v, o));
    return v;
}
__device__ __forceinline__ float dot4(float4 a, float4 b){
    return a.x*b.x + a.y*b.y + a.z*b.z + a.w*b.w;
}
__device__ __forceinline__ void fma4(float4& acc, float s, float4 v){
    acc.x += s*v.x; acc.y += s*v.y; acc.z += s*v.z; acc.w += s*v.w;
}
__device__ __forceinline__ float4 mix4(float om, float4 a, float e, float4 g){
    float4 r; r.x=om*a.x+e*g.x; r.y=om*a.y+e*g.y; r.z=om*a.z+e*g.z; r.w=om*a.w+e*g.w; return r;
}
__device__ __forceinline__ float h4(float4 v){ return v.x+v.y+v.z+v.w; }
__device__ __forceinline__ float sq4(float4 v, float mu){
    float a=v.x-mu, b=v.y-mu, c=v.z-mu, d=v.w-mu; return a*a+b*b+c*c+d*d;
}
__device__ __forceinline__ float4 lnorm4(float4 v, float mu, float inv, float4 w, float4 b){
    float4 r;
    r.x=(v.x-mu)*inv*w.x+b.x; r.y=(v.y-mu)*inv*w.y+b.y;
    r.z=(v.z-mu)*inv*w.z+b.z; r.w=(v.w-mu)*inv*w.w+b.w; return r;
}
__device__ __forceinline__ float4 zero4(){ float4 z; z.x=z.y=z.z=z.w=0.f; return z; }

// ---------------- copy inputs -> g state ----------------
__global__ void k_copyg(const float* __restrict__ gr, const float* __restrict__ gi){
    int t = blockIdx.x*512 + threadIdx.x;
    g_gr[t] = gr[t];
    g_gi[t] = gi[t];
}

// ---------------- init: ysq, zero hist/aux ----------------
__global__ void k_init(const float* __restrict__ cb){
    int gt = blockIdx.x*256 + threadIdx.x;
    int w = gt >> 5, lane = gt & 31;
    const float* row = cb + (size_t)w*TD;
    float p = 0.f;
    for(int j=lane;j<TD;j+=32) p += row[j]*row[j];
    p = warp_sum(p);
    if(lane==0) g_ysq[w] = p;
    if(gt < NK) g_hist[gt] = 0;
    if(gt == 0) g_aux = 0.f;
}

// ---------------- write-address net ----------------
__global__ void __launch_bounds__(256) k_addr(const float* __restrict__ aw,
                                              const float* __restrict__ ab,
                                              const float* __restrict__ gw,
                                              const float* __restrict__ gb)
{
    extern __shared__ float sm[];
    float* s_aw   = sm;                // 64*512
    float* s_gw   = sm + 32768;        // 512
    float* s_flat = s_gw + 512;        // 512
    float* s_log  = s_flat + 512;      // 64
    int t = threadIdx.x, wid = t>>5, lane = t&31;

    {
        const float4* a4 = (const float4*)aw; float4* s4 = (float4*)s_aw;
        for(int i=t;i<8192;i+=256) s4[i] = a4[i];
        const float4* g4 = (const float4*)gw; float4* sg = (float4*)s_gw;
        if(t<128) sg[t] = g4[t];
    }
    __syncthreads();

    float ent_acc = 0.f;
    float gbv = gb[0];

    for(int bi=0;bi<8;bi++){
        int b = blockIdx.x*8 + bi;
        s_flat[t]     = g_gr[b*ND + t];
        s_flat[256+t] = g_gi[b*ND + t];
        __syncthreads();

        #pragma unroll
        for(int r=0;r<8;r++){
            int s = wid*8 + r;
            const float* row = s_aw + s*TD;
            float p = 0.f;
            #pragma unroll 4
            for(int j=lane;j<TD;j+=32) p += s_flat[j]*row[j];
            p = warp_sum(p);
            if(lane==0) s_log[s] = p + ab[s];
        }
        __syncthreads();

        if(wid==0){
            float gp = 0.f;
            #pragma unroll 4
            for(int j=lane;j<TD;j+=32) gp += s_flat[j]*s_gw[j];
            gp = warp_sum(gp);
            float gate = 1.f/(1.f + expf(-(gp + gbv)));
            float v0 = s_log[lane], v1 = s_log[lane+32];
            float m  = warp_max(fmaxf(v0,v1));
            float e0 = expf(v0-m), e1 = expf(v1-m);
            float ssum = warp_sum(e0+e1);
            float w0 = e0/ssum, w1 = e1/ssum;
            ent_acc += -(w0*logf(w0+1e-10f)) - (w1*logf(w1+1e-10f));
            float a0=w0, a1=w1; int i0=lane, i1=lane+32;
            float tv[3]; int ti[3];
            #pragma unroll
            for(int p3=0;p3<3;p3++){
                float v; int ix;
                if(a0>a1 || (a0==a1 && i0<i1)){ v=a0; ix=i0; } else { v=a1; ix=i1; }
                #pragma unroll
                for(int o=16;o;o>>=1){
                    float ov = __shfl_xor_sync(0xffffffffu, v, o);
                    int   oi = __shfl_xor_sync(0xffffffffu, ix, o);
                    if(ov>v || (ov==v && oi<ix)){ v=ov; ix=oi; }
                }
                tv[p3]=v; ti[p3]=ix;
                if(i0==ix) a0 = -1.f;
                if(i1==ix) a1 = -1.f;
            }
            float norm = 1.f/(tv[0]+tv[1]+tv[2]+1e-6f);
            float o0=0.f, o1=0.f;
            #pragma unroll
            for(int p3=0;p3<3;p3++){
                if(lane==ti[p3])    o0 = tv[p3]*norm;
                if(lane+32==ti[p3]) o1 = tv[p3]*norm;
            }
            g_eff[b*NS+lane]    = gate*o0;
            g_eff[b*NS+lane+32] = gate*o1;
        }
        __syncthreads();
    }
    if(wid==0){
        float es = warp_sum(ent_acc);
        if(lane==0) atomicAdd(&g_aux, es*(1.f/(float)NB));
    }
}

// ---------------- fused assoc-mem + complex layernorm (streaming, 2 CTA/SM) --
__global__ void __launch_bounds__(512,2) k_mem(const float* __restrict__ mr_in,
                                               const float* __restrict__ mi_in,
                                               int first,
                                               const float* __restrict__ lnrw, const float* __restrict__ lnrb,
                                               const float* __restrict__ lniw, const float* __restrict__ lnib,
                                               const float* __restrict__ clns, const float* __restrict__ clnb)
{
    __shared__ float s_g[TD];
    __shared__ float s_sim[NS];
    __shared__ float s_attn[NS];
    __shared__ float s_eff[NS];
    __shared__ float s_part[16*TD];    // per-warp read partials (32KB)
    __shared__ float s_red2[16];
    __shared__ float s_scal[2];

    int b = blockIdx.x, t = threadIdx.x, wid = t>>5, lane = t&31;
    const float* mrs = first ? (mr_in + (size_t)b*SD) : (g_mr + (size_t)b*SD);
    const float* mis = first ? (mi_in + (size_t)b*SD) : (g_mi + (size_t)b*SD);

    if(t<ND) s_g[t] = g_gr[b*ND+t]; else s_g[t] = g_gi[b*ND + (t-ND)];
    if(t<NS) s_eff[t] = g_eff[b*NS+t];
    __syncthreads();

    const float4* sg4 = (const float4*)s_g;
    float4 gg0 = sg4[lane], gg1 = sg4[lane+32];       // g real, d=4*lane / 128+4*lane
    float4 hh0 = sg4[64+lane], hh1 = sg4[64+lane+32]; // g imag

    // -------- phase 1: sim (DRAM stream) --------
    #pragma unroll
    for(int r=0;r<4;r++){
        int s = wid*4 + r;
        const float4* pr = (const float4*)(mrs + s*ND);
        const float4* pi = (const float4*)(mis + s*ND);
        float4 a0 = pr[lane], a1 = pr[lane+32];
        float4 c0 = pi[lane], c1 = pi[lane+32];
        float p = dot4(a0,gg0) + dot4(a1,gg1) + dot4(c0,hh0) + dot4(c1,hh1);
        p = warp_sum(p);
        if(lane==0) s_sim[s] = p;
    }
    __syncthreads();

    // -------- softmax over S=64 (warp 0) --------
    if(wid==0){
        float v0 = s_sim[lane], v1 = s_sim[lane+32];
        float m  = warp_max(fmaxf(v0,v1));
        float e0 = expf(v0-m), e1 = expf(v1-m);
        float ssum = warp_sum(e0+e1);
        s_attn[lane]    = e0/ssum;
        s_attn[lane+32] = e1/ssum;
    }
    __syncthreads();

    // -------- phase 2: read accumulation + update + per-row LN (L2 re-read) --
    float4 ar0=zero4(), ar1=zero4(), ai0=zero4(), ai1=zero4();
    #pragma unroll
    for(int r=0;r<4;r++){
        int s = wid*4 + r;
        float e = s_eff[s], om = 1.f - e, at = s_attn[s];
        const float4* pr = (const float4*)(mrs + s*ND);
        const float4* pi = (const float4*)(mis + s*ND);
        float4 a0 = pr[lane], a1 = pr[lane+32];
        float4 c0 = pi[lane], c1 = pi[lane+32];
        // attn-weighted read partial (OLD memory)
        fma4(ar0, at, a0); fma4(ar1, at, a1);
        fma4(ai0, at, c0); fma4(ai1, at, c1);
        // real update + LN
        {
            float4 v0 = mix4(om, a0, e, gg0), v1 = mix4(om, a1, e, gg1);
            float mu  = warp_sum(h4(v0)+h4(v1)) * (1.f/ND);
            float var = warp_sum(sq4(v0,mu)+sq4(v1,mu)) * (1.f/ND);
            float inv = 1.f/sqrtf(var + 1e-6f);
            const float4* w4 = (const float4*)lnrw; const float4* b4 = (const float4*)lnrb;
            float4 w0=__ldg(&w4[lane]), w1=__ldg(&w4[lane+32]);
            float4 bb0=__ldg(&b4[lane]), bb1=__ldg(&b4[lane+32]);
            float4* dst = (float4*)(g_mr + (size_t)b*SD + s*ND);
            dst[lane]    = lnorm4(v0, mu, inv, w0, bb0);
            dst[lane+32] = lnorm4(v1, mu, inv, w1, bb1);
        }
        // imag update + LN
        {
            float4 v0 = mix4(om, c0, e, hh0), v1 = mix4(om, c1, e, hh1);
            float mu  = warp_sum(h4(v0)+h4(v1)) * (1.f/ND);
            float var = warp_sum(sq4(v0,mu)+sq4(v1,mu)) * (1.f/ND);
            float inv = 1.f/sqrtf(var + 1e-6f);
            const float4* w4 = (const float4*)lniw; const float4* b4 = (const float4*)lnib;
            float4 w0=__ldg(&w4[lane]), w1=__ldg(&w4[lane+32]);
            float4 bb0=__ldg(&b4[lane]), bb1=__ldg(&b4[lane+32]);
            float4* dst = (float4*)(g_mi + (size_t)b*SD + s*ND);
            dst[lane]    = lnorm4(v0, mu, inv, w0, bb0);
            dst[lane+32] = lnorm4(v1, mu, inv, w1, bb1);
        }
    }

    // -------- deterministic cross-warp reduce of read partials --------
    {
        float4* sp4 = (float4*)&s_part[wid*TD];
        sp4[lane]    = ar0; sp4[lane+32]    = ar1;
        sp4[64+lane] = ai0; sp4[64+lane+32] = ai1;
    }
    __syncthreads();
    float red = 0.f;
    #pragma unroll
    for(int w=0;w<16;w++) red += s_part[w*TD + t];
    __syncthreads();
    s_part[t] = red;          // s_part[0..255]=read_r, [256..511]=read_i
    __syncthreads();

    // -------- complex layernorm on z = g + read --------
    float zr=0.f, zi=0.f, mag=0.f;
    if(t < ND){
        zr = s_g[t]      + s_part[t];
        zi = s_g[ND+t]   + s_part[ND+t];
        mag = sqrtf(zr*zr + zi*zi + 1e-8f);
    }
    float p = warp_sum(mag);
    if(lane==0) s_red2[wid] = p;
    __syncthreads();
    if(t==0){
        float m2=0.f;
        #pragma unroll
        for(int i=0;i<8;i++) m2 += s_red2[i];
        s_scal[0] = m2*(1.f/ND);
    }
    __syncthreads();
    float mean = s_scal[0];
    float dv = (t<ND) ? (mag-mean)*(mag-mean) : 0.f;
    p = warp_sum(dv);
    if(lane==0) s_red2[wid] = p;
    __syncthreads();
    if(t==0){
        float v2=0.f;
        #pragma unroll
        for(int i=0;i<8;i++) v2 += s_red2[i];
        s_scal[1] = 1.f/sqrtf(v2*(1.f/(ND-1)) + 1e-4f);
    }
    __syncthreads();
    if(t < ND){
        float nm = (mag-mean)*s_scal[1]*__ldg(&clns[t]) + __ldg(&clnb[t]);
        float h2 = zr*zr + zi*zi;
        float c, s;
        if(h2 > 0.f){ float ih = 1.f/sqrtf(h2); c = zr*ih; s = zi*ih; }
        else { c = 1.f; s = 0.f; }
        g_zf[(size_t)b*TD + t]      = nm*c;
        g_zf[(size_t)b*TD + ND + t] = nm*s;
    }
}

// ---------------- VQ distance GEMM + per-tile argmin (prefetched) -----------
#define VQ_DK 16
#define VQ_LD 132
__global__ void __launch_bounds__(256) k_vq(const float* __restrict__ cb){
    __shared__ float s_a[VQ_DK][VQ_LD];
    __shared__ float s_b[VQ_DK][VQ_LD];
    int tid = threadIdx.x;
    int tx = tid & 15, ty = tid >> 4;
    int b0 = blockIdx.x*128, k0 = blockIdx.y*128;

    float acc[8][8];
    #pragma unroll
    for(int i=0;i<8;i++)
        #pragma unroll
        for(int j=0;j<8;j++) acc[i][j] = 0.f;

    int r_[2], c_[2];
    float4 pa[2], pb[2];
    #pragma unroll
    for(int l=0;l<2;l++){
        int q = tid*2 + l;
        r_[l] = q >> 2; c_[l] = (q & 3) * 4;
        pa[l] = *(const float4*)&g_zf[(size_t)(b0+r_[l])*TD + c_[l]];
        pb[l] = *(const float4*)&cb  [(size_t)(k0+r_[l])*TD + c_[l]];
    }

    for(int ch=0; ch<TD/VQ_DK; ch++){
        __syncthreads();
        #pragma unroll
        for(int l=0;l<2;l++){
            s_a[c_[l]+0][r_[l]]=pa[l].x; s_a[c_[l]+1][r_[l]]=pa[l].y;
            s_a[c_[l]+2][r_[l]]=pa[l].z; s_a[c_[l]+3][r_[l]]=pa[l].w;
            s_b[c_[l]+0][r_[l]]=pb[l].x; s_b[c_[l]+1][r_[l]]=pb[l].y;
            s_b[c_[l]+2][r_[l]]=pb[l].z; s_b[c_[l]+3][r_[l]]=pb[l].w;
        }
        __syncthreads();
        if(ch < TD/VQ_DK - 1){
            int d0 = (ch+1)*VQ_DK;
            #pragma unroll
            for(int l=0;l<2;l++){
                pa[l] = *(const float4*)&g_zf[(size_t)(b0+r_[l])*TD + d0 + c_[l]];
                pb[l] = *(const float4*)&cb  [(size_t)(k0+r_[l])*TD + d0 + c_[l]];
            }
        }
        #pragma unroll
        for(int d=0; d<VQ_DK; d++){
            float af[8], bf[8];
            *(float4*)&af[0] = *(const float4*)&s_a[d][ty*8];
            *(float4*)&af[4] = *(const float4*)&s_a[d][ty*8+4];
            *(float4*)&bf[0] = *(const float4*)&s_b[d][tx*8];
            *(float4*)&bf[4] = *(const float4*)&s_b[d][tx*8+4];
            #pragma unroll
            for(int i=0;i<8;i++)
                #pragma unroll
                for(int j=0;j<8;j++) acc[i][j] += af[i]*bf[j];
        }
    }

    float ysq[8];
    #pragma unroll
    for(int j=0;j<8;j++) ysq[j] = __ldg(&g_ysq[k0 + tx*8 + j]);

    #pragma unroll
    for(int i=0;i<8;i++){
        float bv = FLT_MAX; int bi = 0x7fffffff;
        #pragma unroll
        for(int j=0;j<8;j++){
            float dvv = ysq[j] - 2.f*acc[i][j];
            int kk = k0 + tx*8 + j;
            if(dvv < bv){ bv = dvv; bi = kk; }
        }
        #pragma unroll
        for(int o=1;o<16;o<<=1){
            float ov = __shfl_xor_sync(0xffffffffu, bv, o);
            int   oi = __shfl_xor_sync(0xffffffffu, bi, o);
            if(ov<bv || (ov==bv && oi<bi)){ bv=ov; bi=oi; }
        }
        if(tx==0){
            int b = b0 + ty*8 + i;
            g_pscore[b*8 + blockIdx.y] = bv;
            g_pidx  [b*8 + blockIdx.y] = bi;
        }
    }
}

// ---------------- final argmin, gather codebook, loss, histogram -------------
__global__ void __launch_bounds__(256) k_pick(const float* __restrict__ cb){
    int wid = threadIdx.x>>5, lane = threadIdx.x&31;
    int b = blockIdx.x*8 + wid;
    float bv = FLT_MAX; int bi = 0x7fffffff;
    if(lane < 8){ bv = g_pscore[b*8+lane]; bi = g_pidx[b*8+lane]; }
    #pragma unroll
    for(int o=1;o<32;o<<=1){
        float ov = __shfl_xor_sync(0xffffffffu, bv, o);
        int   oi = __shfl_xor_sync(0xffffffffu, bi, o);
        if(ov<bv || (ov==bv && oi<bi)){ bv=ov; bi=oi; }
    }
    bi = __shfl_sync(0xffffffffu, bi, 0);
    const float* row = cb + (size_t)bi*TD;
    float lacc = 0.f;
    for(int j=lane;j<TD;j+=32){
        float c = row[j], z = g_zf[(size_t)b*TD + j];
        float df = c - z; lacc += df*df;
        if(j < ND) g_gr[b*ND + j] = c;
        else       g_gi[b*ND + j - ND] = c;
    }
    lacc = warp_sum(lacc);
    if(lane==0){
        atomicAdd(&g_aux, BETA * lacc * (1.f/TD) * (1.f/NB));
        atomicAdd(&g_hist[bi], 1);
    }
}

// ---------------- codebook-usage entropy + hist reset ----------------
__global__ void __launch_bounds__(1024) k_ent(){
    __shared__ float s_red[32];
    int t = threadIdx.x;
    float pp = (float)g_hist[t] * (1.f/NB);
    float e = -pp * logf(pp + 1e-10f);
    g_hist[t] = 0;
    e = warp_sum(e);
    if((t&31)==0) s_red[t>>5] = e;
    __syncthreads();
    if(t < 32){
        float v = s_red[t];
        v = warp_sum(v);
        if(t==0) g_aux = g_aux + v * (1.f/6.931471805599453f);  // /log(1024)
    }
}

// ---------------- write output ----------------
__global__ void k_out(float* __restrict__ out, int out_n){
    int t = blockIdx.x*256 + threadIdx.x;
    int b = t >> 9, j = t & 511;
    out[t] = (j < ND) ? g_gr[b*ND + j] : g_gi[b*ND + j - ND];
    if(t == 0 && out_n > NB*TD) out[out_n-1] = g_aux;
}

// =============================================================================
extern "C" void kernel_launch(void* const* d_in, const int* in_sizes, int n_in,
                              void* d_out, int out_size)
{
    const float* gw_real = (const float*)d_in[0];
    const float* gw_imag = (const float*)d_in[1];
    const float* mem_real= (const float*)d_in[2];
    const float* mem_imag= (const float*)d_in[3];
    const float* gate_w  = (const float*)d_in[4];
    const float* gate_b  = (const float*)d_in[5];
    const float* addr_w  = (const float*)d_in[6];
    const float* addr_b  = (const float*)d_in[7];
    const float* lnr_w   = (const float*)d_in[8];
    const float* lnr_b   = (const float*)d_in[9];
    const float* lni_w   = (const float*)d_in[10];
    const float* lni_b   = (const float*)d_in[11];
    const float* cln_s   = (const float*)d_in[12];
    const float* cln_b   = (const float*)d_in[13];
    const float* codebook= (const float*)d_in[14];
    float* out = (float*)d_out;

    const int SMEM_ADDR = (64*512 + 512 + 512 + 64) * 4;
    static int attr_done = 0;
    if(!attr_done){
        cudaFuncSetAttribute(k_addr, cudaFuncAttributeMaxDynamicSharedMemorySize, SMEM_ADDR);
        attr_done = 1;
    }

    k_copyg<<<1024, 512>>>(gw_real, gw_imag);
    k_init <<<128, 256>>>(codebook);

    for(int it=0; it<5; it++){
        k_addr<<<256, 256, SMEM_ADDR>>>(addr_w, addr_b, gate_w, gate_b);
        k_mem <<<NB, 512>>>(mem_real, mem_imag, it==0 ? 1 : 0,
                            lnr_w, lnr_b, lni_w, lni_b, cln_s, cln_b);
        k_vq  <<<dim3(16,8), 256>>>(codebook);
        k_pick<<<256, 256>>>(codebook);
        k_ent <<<1, 1024>>>();
    }
    k_out<<<4096, 256>>>(out, out_size);
}